// round 11
// baseline (speedup 1.0000x reference)
#include <cuda_runtime.h>
#include <math.h>
#include <cstdint>

#define BB  2
#define TT  2048
#define CCH 1024
#define HH  16
#define HSZ 64

// Scratch (alloc-free rule: __device__ globals).
__device__ float g_K[BB * HH * TT * HSZ];       // [b,h,t,hs]
__device__ float g_Q[BB * HH * TT * HSZ];       // [b,h,t,hs]
__device__ float g_V[BB * HH * TT * HSZ];       // [b,h,hs,t]  (TRANSPOSED)
__device__ float g_O[BB * TT * CCH];
__device__ float g_Xc[BB * TT * CCH];           // tf32-rounded X
__device__ float g_Wtqkv[3 * CCH * CCH];        // tf32-rounded W_qkv^T  [n][k]
__device__ float g_Wtproj[CCH * CCH];           // tf32-rounded W_proj^T [n][k]

// ---------------------------------------------------------------------------
// helpers
// ---------------------------------------------------------------------------
__device__ __forceinline__ unsigned f2tf32(float f) {
    unsigned u;
    asm("cvt.rna.tf32.f32 %0, %1;" : "=r"(u) : "f"(f));
    return u;
}
__device__ __forceinline__ float rnd32(float f) {
    return __uint_as_float(f2tf32(f));
}
__device__ __forceinline__ float fex2(float x) {
    float r;
    asm("ex2.approx.f32 %0, %1;" : "=f"(r) : "f"(x));
    return r;
}
__device__ __forceinline__ void mma8(float* c, const unsigned* a, const unsigned* b) {
    asm volatile(
        "mma.sync.aligned.m16n8k8.row.col.f32.tf32.tf32.f32 "
        "{%0,%1,%2,%3}, {%4,%5,%6,%7}, {%8,%9}, {%0,%1,%2,%3};\n"
        : "+f"(c[0]), "+f"(c[1]), "+f"(c[2]), "+f"(c[3])
        : "r"(a[0]), "r"(a[1]), "r"(a[2]), "r"(a[3]), "r"(b[0]), "r"(b[1]));
}
// ldmatrix x4 (b16 view of tf32 data): 4 fragment regs in one op
__device__ __forceinline__ void ldsm4(unsigned* r, uint32_t saddr) {
    asm volatile("ldmatrix.sync.aligned.m8n8.x4.shared.b16 {%0,%1,%2,%3}, [%4];"
        : "=r"(r[0]), "=r"(r[1]), "=r"(r[2]), "=r"(r[3]) : "r"(saddr));
}
__device__ __forceinline__ uint32_t smem_u32(const void* p) {
    uint32_t a;
    asm("{ .reg .u64 t; cvta.to.shared.u64 t, %1; cvt.u32.u64 %0, t; }" : "=r"(a) : "l"(p));
    return a;
}
__device__ __forceinline__ void cpa16(float* s, const float* g) {
    unsigned sa = (unsigned)__cvta_generic_to_shared(s);
    asm volatile("cp.async.cg.shared.global [%0], [%1], 16;\n" :: "r"(sa), "l"(g));
}
__device__ __forceinline__ void cpa16s(uint32_t s, const float* g) {
    asm volatile("cp.async.cg.shared.global [%0], [%1], 16;\n" :: "r"(s), "l"(g));
}
__device__ __forceinline__ void cp_commit() {
    asm volatile("cp.async.commit_group;\n");
}
template <int N>
__device__ __forceinline__ void cp_wait() {
    asm volatile("cp.async.wait_group %0;\n" :: "n"(N));
}
// byte-offset sw128 swizzle (128B rows)
__device__ __forceinline__ uint32_t swz(uint32_t o) { return o ^ ((o >> 3) & 0x70); }

// ---------------------------------------------------------------------------
// Prepass 1: round X to tf32 -> g_Xc
// ---------------------------------------------------------------------------
__global__ void round_x(const float* __restrict__ in, int n)
{
    int i = (blockIdx.x * blockDim.x + threadIdx.x) * 4;
    if (i < n) {
        float4 v = *(const float4*)(in + i);
        v.x = rnd32(v.x); v.y = rnd32(v.y);
        v.z = rnd32(v.z); v.w = rnd32(v.w);
        *(float4*)(g_Xc + i) = v;
    }
}

// ---------------------------------------------------------------------------
// Prepass 2: transpose + round W. in [R][Cc] -> out [Cc][R] (K-major rows).
// ---------------------------------------------------------------------------
template <int DST>
__global__ void transpose_rnd(const float* __restrict__ in, int R, int Cc)
{
    float* out = DST ? g_Wtproj : g_Wtqkv;
    __shared__ float ts[32][33];
    int bx = blockIdx.x * 32, by = blockIdx.y * 32;
    int tx = threadIdx.x, ty = threadIdx.y;
#pragma unroll
    for (int i = 0; i < 4; i++)
        ts[ty + i * 8][tx] = rnd32(in[(long)(by + ty + i * 8) * Cc + bx + tx]);
    __syncthreads();
#pragma unroll
    for (int i = 0; i < 4; i++)
        out[(long)(bx + ty + i * 8) * R + by + tx] = ts[tx][ty + i * 8];
}

// ---------------------------------------------------------------------------
// TF32 GEMM via mma.sync + ldmatrix: C[M,N] = A[M,K] @ Bt[N,K]^T.
// Both operands K-major in smem, 128B rows, sw128-swizzled.
// 3-stage cp.async pipeline, ONE __syncthreads per k-iter:
//   wait<1> -> sync -> issue(t+2) -> compute(t)
// (top sync proves all warps finished iter t-1, whose buffer issue overwrites)
// MODE 0: A=g_Xc, Bt=g_Wtqkv, scatter -> g_K/g_Q (rounded) + g_V transposed.
// MODE 1: A=g_O,  Bt=g_Wtproj, C=out.
// Block 256 (8 warps, 2x4), tile 128x128, BK=32.
// ---------------------------------------------------------------------------
#define GSTG_A 16384
#define GSTG   32768
#define GEMM_SMEM (3 * GSTG)

template <int MODE>
__global__ __launch_bounds__(256, 2) void gemm_lm(float* __restrict__ C)
{
    extern __shared__ float smemf[];
    const float* A  = (MODE == 0) ? g_Xc : g_O;
    const float* Bt = (MODE == 0) ? g_Wtqkv : g_Wtproj;
    const int K = CCH;
    const int N = (MODE == 0) ? 3 * CCH : CCH;

    const uint32_t sb = smem_u32(smemf);
    const int tid = threadIdx.x, lane = tid & 31, w = tid >> 5;
    const int wr = w >> 2, wc = w & 3, g = lane >> 2, tg = lane & 3;
    const int m4 = lane >> 3, ln7 = lane & 7;
    const int bm0 = blockIdx.y * 128, bn0 = blockIdx.x * 128;

    float acc[4][4][4];
#pragma unroll
    for (int mt = 0; mt < 4; mt++)
#pragma unroll
        for (int nt = 0; nt < 4; nt++)
#pragma unroll
            for (int q = 0; q < 4; q++) acc[mt][nt][q] = 0.f;

    const int nk = K / 32;

    auto issue_stage = [&](int t) {
        if (t < nk) {
            uint32_t base = sb + (t % 3) * GSTG;
            int kb = t * 32;
#pragma unroll
            for (int i = 0; i < 4; i++) {
                int id = tid + i * 256;
                int r = id >> 3, c = id & 7;
                cpa16s(base + swz(r * 128 + c * 16),
                       A + (long)(bm0 + r) * K + kb + c * 4);
            }
#pragma unroll
            for (int i = 0; i < 4; i++) {
                int id = tid + i * 256;
                int r = id >> 3, c = id & 7;
                cpa16s(base + GSTG_A + swz(r * 128 + c * 16),
                       Bt + (long)(bn0 + r) * K + kb + c * 4);
            }
        }
        cp_commit();   // empty group at tail keeps wait<1> accounting sound
    };

    issue_stage(0);
    issue_stage(1);

    for (int t = 0; t < nk; t++) {
        cp_wait<1>();      // stage t landed (t+1 may be in flight)
        __syncthreads();   // all warps done with iter t-1 (buffer (t+2)%3)
        issue_stage(t + 2);

        uint32_t Ab = sb + (t % 3) * GSTG;
        uint32_t Bb = Ab + GSTG_A;
#pragma unroll
        for (int ks = 0; ks < 4; ks++) {
            const int k0 = ks * 8;
            unsigned af[4][4], bf[2][4];
            const int c4A = k0 + (m4 >> 1) * 4;
            const int c4B = k0 + (m4 & 1) * 4;
#pragma unroll
            for (int mt = 0; mt < 4; mt++) {
                int rA = wr * 64 + mt * 16 + (m4 & 1) * 8 + ln7;
                ldsm4(af[mt], Ab + swz(rA * 128 + c4A * 4));
            }
#pragma unroll
            for (int ntp = 0; ntp < 2; ntp++) {
                int rB = wc * 32 + (2 * ntp + (m4 >> 1)) * 8 + ln7;
                ldsm4(bf[ntp], Bb + swz(rB * 128 + c4B * 4));
            }
#pragma unroll
            for (int mt = 0; mt < 4; mt++)
#pragma unroll
                for (int ntp = 0; ntp < 2; ntp++) {
                    mma8(acc[mt][2 * ntp],     af[mt], bf[ntp]);
                    mma8(acc[mt][2 * ntp + 1], af[mt], bf[ntp] + 2);
                }
        }
    }

    // epilogue
#pragma unroll
    for (int mt = 0; mt < 4; mt++) {
#pragma unroll
        for (int nt = 0; nt < 4; nt++) {
            int row = bm0 + wr * 64 + mt * 16 + g;
            int col = bn0 + wc * 32 + nt * 8 + 2 * tg;
            if constexpr (MODE == 1) {
                *(float2*)(C + (long)row * N + col) =
                    make_float2(acc[mt][nt][0], acc[mt][nt][1]);
                *(float2*)(C + (long)(row + 8) * N + col) =
                    make_float2(acc[mt][nt][2], acc[mt][nt][3]);
            } else {
                int which = col >> 10;           // 0=K, 1=Q, 2=V
                int cc = col & 1023;
                int h = cc >> 6, d = cc & 63;
                int b = row >> 11, t_ = row & 2047;
                if (which == 2) {
                    // V transposed: [b,h,hs,t]
                    long base = ((long)(b * HH + h) * HSZ + d) * TT + t_;
                    g_V[base]          = rnd32(acc[mt][nt][0]);
                    g_V[base + TT]     = rnd32(acc[mt][nt][1]);
                    g_V[base + 8]      = rnd32(acc[mt][nt][2]);
                    g_V[base + TT + 8] = rnd32(acc[mt][nt][3]);
                } else {
                    float* dst = (which == 0) ? g_K : g_Q;
                    long base = ((long)(b * HH + h) * TT + t_) * HSZ + d;
                    *(float2*)(dst + base) =
                        make_float2(rnd32(acc[mt][nt][0]), rnd32(acc[mt][nt][1]));
                    *(float2*)(dst + base + 8 * HSZ) =
                        make_float2(rnd32(acc[mt][nt][2]), rnd32(acc[mt][nt][3]));
                }
            }
        }
    }
}

// ---------------------------------------------------------------------------
// Flash attention (causal) with ldmatrix fragment loads.
// Grid: (T/64, B*H). Block: 128 threads (4 warps), warp owns 16 q-rows.
// Smem tiles [64 rows][64 floats], swizzle: float c -> c ^ ((r&7)<<2).
// 2-stage KV, ONE __syncthreads per j-iter:
//   wait<0> -> sync -> issue(j+1) -> compute(j)
// K tile rows = kpos; V tile rows = headdim (g_V is transposed).
// ---------------------------------------------------------------------------
#define ATTN_SMEM (5 * 64 * 64 * 4)

__global__ __launch_bounds__(128, 2) void attn_kernel()
{
    extern __shared__ float asmem[];
    float* QP = asmem;                 // 64*64
    float* Ks = asmem + 4096;          // [2][64*64]
    float* Vs = asmem + 3 * 4096;      // [2][64*64]
    const uint32_t QPb = smem_u32(QP);
    const uint32_t Ksb = smem_u32(Ks);
    const uint32_t Vsb = smem_u32(Vs);

    const int tid  = threadIdx.x;
    const int lane = tid & 31;
    const int w    = tid >> 5;
    const int g    = lane >> 2;
    const int tg   = lane & 3;
    const int m4   = lane >> 3, ln7 = lane & 7;
    const int qi   = gridDim.x - 1 - blockIdx.x;   // longest first
    const int bh   = blockIdx.y;

    const float* Qg = g_Q + (long)bh * TT * HSZ;
    const float* Kg = g_K + (long)bh * TT * HSZ;
    const float* Vg = g_V + (long)bh * TT * HSZ;   // transposed [hs][t]

    auto issue_kv = [&](int j, int st) {
#pragma unroll
        for (int i = 0; i < 8; i++) {
            int f = tid + i * 128;
            int r = f >> 4, c = (f & 15) << 2;
            int idx = st * 4096 + r * 64 + (c ^ ((r & 7) << 2));
            cpa16(Ks + idx, Kg + (long)(j * 64 + r) * HSZ + c);
            cpa16(Vs + idx, Vg + (long)r * TT + j * 64 + c);
        }
    };

    issue_kv(0, 0);
    cp_commit();

    // load Q tile (swizzled)
#pragma unroll
    for (int i = 0; i < 16; i++) {
        int f = tid + i * 128;
        int r = f >> 5, d = (f & 31) << 1;
        float2 v = *(const float2*)(Qg + (long)(qi * 64 + r) * HSZ + d);
        *(float2*)&QP[r * 64 + (d ^ ((r & 7) << 2))] = v;
    }
    __syncthreads();

    // Q A-fragments via ldmatrix (rows w*16..w*16+15)
    unsigned qa[8][4];
    {
        const int row = w * 16 + (m4 & 1) * 8 + ln7;
#pragma unroll
        for (int kt = 0; kt < 8; kt++) {
            int c4 = kt * 8 + (m4 >> 1) * 4;
            ldsm4(qa[kt], QPb + ((row * 64 + (c4 ^ ((row & 7) << 2))) << 2));
        }
    }

    float o[8][4];
#pragma unroll
    for (int nt = 0; nt < 8; nt++)
#pragma unroll
        for (int q = 0; q < 4; q++) o[nt][q] = 0.f;
    float mrow0 = -1e30f, mrow1 = -1e30f;
    float lrow0 = 0.f,    lrow1 = 0.f;
    const float SCL2E = (1.0f / 32.0f) * 1.4426950408889634f;
    const int qg0 = qi * 64 + w * 16 + g;

    for (int j = 0; j <= qi; j++) {
        cp_wait<0>();      // KV tile j landed
        __syncthreads();   // all warps done with iter j-1
        if (j < qi) {
            issue_kv(j + 1, (j + 1) & 1);   // overwrites stage read in j-1: safe
            cp_commit();
        }

        const uint32_t Kb = Ksb + (j & 1) * 16384;
        const uint32_t Vb = Vsb + (j & 1) * 16384;

        // S = Q @ K^T  (ldmatrix K-frags: 2 n-tiles per x4)
        float s[8][4];
#pragma unroll
        for (int nt = 0; nt < 8; nt++)
#pragma unroll
            for (int q = 0; q < 4; q++) s[nt][q] = 0.f;
#pragma unroll
        for (int kt = 0; kt < 8; kt++) {
            int c4 = kt * 8 + (m4 & 1) * 4;
#pragma unroll
            for (int ntp = 0; ntp < 4; ntp++) {
                unsigned kb4[4];
                int row = (2 * ntp + (m4 >> 1)) * 8 + ln7;
                ldsm4(kb4, Kb + ((row * 64 + (c4 ^ ((row & 7) << 2))) << 2));
                mma8(s[2 * ntp],     qa[kt], kb4);
                mma8(s[2 * ntp + 1], qa[kt], kb4 + 2);
            }
        }

        // causal mask (diagonal tile only)
        if (j == qi) {
#pragma unroll
            for (int nt = 0; nt < 8; nt++) {
                int kg = j * 64 + nt * 8 + 2 * tg;
                if (kg     > qg0    ) s[nt][0] = -1e30f;
                if (kg + 1 > qg0    ) s[nt][1] = -1e30f;
                if (kg     > qg0 + 8) s[nt][2] = -1e30f;
                if (kg + 1 > qg0 + 8) s[nt][3] = -1e30f;
            }
        }

        // online softmax
        float rm0 = -1e30f, rm1 = -1e30f;
#pragma unroll
        for (int nt = 0; nt < 8; nt++) {
            rm0 = fmaxf(rm0, fmaxf(s[nt][0], s[nt][1]));
            rm1 = fmaxf(rm1, fmaxf(s[nt][2], s[nt][3]));
        }
        rm0 = fmaxf(rm0, __shfl_xor_sync(0xffffffffu, rm0, 1));
        rm0 = fmaxf(rm0, __shfl_xor_sync(0xffffffffu, rm0, 2));
        rm1 = fmaxf(rm1, __shfl_xor_sync(0xffffffffu, rm1, 1));
        rm1 = fmaxf(rm1, __shfl_xor_sync(0xffffffffu, rm1, 2));

        float mn0 = fmaxf(mrow0, rm0), mn1 = fmaxf(mrow1, rm1);
        float f0 = fex2((mrow0 - mn0) * SCL2E);
        float f1 = fex2((mrow1 - mn1) * SCL2E);
        mrow0 = mn0; mrow1 = mn1;

        float sum0 = 0.f, sum1 = 0.f;
        {
            const int r0 = w * 16 + g;
            const int x0 = (r0 & 7) << 2;
            const int x1 = ((r0 + 8) & 7) << 2;
#pragma unroll
            for (int nt = 0; nt < 8; nt++) {
                float p0 = fex2((s[nt][0] - mn0) * SCL2E);
                float p1 = fex2((s[nt][1] - mn0) * SCL2E);
                float p2 = fex2((s[nt][2] - mn1) * SCL2E);
                float p3 = fex2((s[nt][3] - mn1) * SCL2E);
                sum0 += p0 + p1;
                sum1 += p2 + p3;
                int c = nt * 8 + 2 * tg;
                *(float2*)&QP[ r0      * 64 + (c ^ x0)] = make_float2(rnd32(p0), rnd32(p1));
                *(float2*)&QP[(r0 + 8) * 64 + (c ^ x1)] = make_float2(rnd32(p2), rnd32(p3));
            }
        }
        sum0 += __shfl_xor_sync(0xffffffffu, sum0, 1);
        sum0 += __shfl_xor_sync(0xffffffffu, sum0, 2);
        sum1 += __shfl_xor_sync(0xffffffffu, sum1, 1);
        sum1 += __shfl_xor_sync(0xffffffffu, sum1, 2);
        lrow0 = lrow0 * f0 + sum0;
        lrow1 = lrow1 * f1 + sum1;

#pragma unroll
        for (int nt = 0; nt < 8; nt++) {
            o[nt][0] *= f0; o[nt][1] *= f0;
            o[nt][2] *= f1; o[nt][3] *= f1;
        }
        __syncwarp();

        // O += P @ V  (pa + vb via ldmatrix; V tile rows = headdim)
        {
            const int rowp = w * 16 + (m4 & 1) * 8 + ln7;
#pragma unroll
            for (int kt = 0; kt < 8; kt++) {
                int k0 = kt * 8;
                unsigned pa[4];
                int c4p = k0 + (m4 >> 1) * 4;
                ldsm4(pa, QPb + ((rowp * 64 + (c4p ^ ((rowp & 7) << 2))) << 2));
                int c4v = k0 + (m4 & 1) * 4;
#pragma unroll
                for (int ntp = 0; ntp < 4; ntp++) {
                    unsigned vb4[4];
                    int row = (2 * ntp + (m4 >> 1)) * 8 + ln7;
                    ldsm4(vb4, Vb + ((row * 64 + (c4v ^ ((row & 7) << 2))) << 2));
                    mma8(o[2 * ntp],     pa, vb4);
                    mma8(o[2 * ntp + 1], pa, vb4 + 2);
                }
            }
        }
    }

    // finalize: divide by l, tf32-round at write (proj GEMM reads raw)
    float il0 = 1.0f / lrow0;
    float il1 = 1.0f / lrow1;
    const int b = bh >> 4, h = bh & 15;
    const int row0 = qi * 64 + w * 16 + g;
#pragma unroll
    for (int nt = 0; nt < 8; nt++) {
        int d = nt * 8 + 2 * tg;
        long idx0 = ((long)(b * TT + row0    ) * CCH) + h * HSZ + d;
        long idx1 = ((long)(b * TT + row0 + 8) * CCH) + h * HSZ + d;
        *(float2*)(g_O + idx0) =
            make_float2(rnd32(o[nt][0] * il0), rnd32(o[nt][1] * il0));
        *(float2*)(g_O + idx1) =
            make_float2(rnd32(o[nt][2] * il1), rnd32(o[nt][3] * il1));
    }
}

// ---------------------------------------------------------------------------
extern "C" void kernel_launch(void* const* d_in, const int* in_sizes, int n_in,
                              void* d_out, int out_size)
{
    (void)in_sizes; (void)n_in; (void)out_size;
    const float* X     = (const float*)d_in[0];
    const float* Wqkv  = (const float*)d_in[1];
    const float* Wproj = (const float*)d_in[2];
    float* out = (float*)d_out;

    static bool attrs_set = false;
    if (!attrs_set) {
        cudaFuncSetAttribute(gemm_lm<0>,
            cudaFuncAttributeMaxDynamicSharedMemorySize, GEMM_SMEM);
        cudaFuncSetAttribute(gemm_lm<1>,
            cudaFuncAttributeMaxDynamicSharedMemorySize, GEMM_SMEM);
        cudaFuncSetAttribute(attn_kernel,
            cudaFuncAttributeMaxDynamicSharedMemorySize, ATTN_SMEM);
        attrs_set = true;
    }

    // 0) prepass: round X; transpose+round weights into K-major
    round_x<<<(BB * TT * CCH / 4 + 255) / 256, 256>>>(X, BB * TT * CCH);
    transpose_rnd<0><<<dim3(3 * CCH / 32, CCH / 32), dim3(32, 8)>>>(Wqkv,  CCH, 3 * CCH);
    transpose_rnd<1><<<dim3(CCH / 32,     CCH / 32), dim3(32, 8)>>>(Wproj, CCH, CCH);

    // 1) QKV = Xc @ Wqkv, scattered to g_K/g_Q [b,h,t,hs] + g_V [b,h,hs,t]
    gemm_lm<0><<<dim3(3 * CCH / 128, BB * TT / 128), 256, GEMM_SMEM>>>(nullptr);

    // 2) causal flash attention -> g_O [b,t,c]
    attn_kernel<<<dim3(TT / 64, BB * HH), 128, ATTN_SMEM>>>();

    // 3) out = g_O @ Wproj
    gemm_lm<1><<<dim3(CCH / 128, BB * TT / 128), 256, GEMM_SMEM>>>(out);
}